// round 10
// baseline (speedup 1.0000x reference)
#include <cuda_runtime.h>
#include <cstdint>

#define NV 2048
#define NE 8192
#define D  128

// ---------------- device scratch (static: no runtime allocation) ----------------
__device__ __align__(16) float g_w[NE];                    // 32 KB
__device__ __align__(16) float g_Tw[(size_t)NV * NE];      // 64 MB  tf32(T*w)
__device__ __align__(16) float g_Ttf[(size_t)NV * NE];     // 64 MB  tf32(T)
__device__ __align__(16) float g_adjA[(size_t)NV * NV];    // 16 MB
__device__ __align__(16) float g_HW[NV * D];               // 1 MB

// ---------------- helpers ----------------
__device__ __forceinline__ uint32_t f2tf32(float x) {
    uint32_t u;
    asm("cvt.rna.tf32.f32 %0, %1;" : "=r"(u) : "f"(x));
    return u;
}

__device__ __forceinline__ void mma_tf32(float* d, const uint32_t* a, const uint32_t* b) {
    asm volatile(
        "mma.sync.aligned.m16n8k8.row.col.f32.tf32.tf32.f32 "
        "{%0,%1,%2,%3}, {%4,%5,%6,%7}, {%8,%9}, {%0,%1,%2,%3};\n"
        : "+f"(d[0]), "+f"(d[1]), "+f"(d[2]), "+f"(d[3])
        : "r"(a[0]), "r"(a[1]), "r"(a[2]), "r"(a[3]), "r"(b[0]), "r"(b[1]));
}

__device__ __forceinline__ void ldsm4(uint32_t* r, uint32_t saddr) {
    asm volatile("ldmatrix.sync.aligned.m8n8.x4.shared.b16 {%0,%1,%2,%3}, [%4];"
                 : "=r"(r[0]), "=r"(r[1]), "=r"(r[2]), "=r"(r[3]) : "r"(saddr));
}

__device__ __forceinline__ void cp_async16(uint32_t saddr, const void* g) {
    asm volatile("cp.async.cg.shared.global [%0], [%1], 16;\n" :: "r"(saddr), "l"(g));
}
__device__ __forceinline__ void cp_commit() { asm volatile("cp.async.commit_group;\n" ::: "memory"); }
__device__ __forceinline__ void cp_wait1()  { asm volatile("cp.async.wait_group 1;\n" ::: "memory"); }
__device__ __forceinline__ void cp_wait0()  { asm volatile("cp.async.wait_group 0;\n" ::: "memory"); }

__device__ __forceinline__ uint32_t smem_u32(const void* p) {
    uint32_t a;
    asm("{ .reg .u64 t; cvta.to.shared.u64 t, %1; cvt.u32.u64 %0, t; }" : "=r"(a) : "l"(p));
    return a;
}

// ---------------- kernel 1: w = H_e @ p  (warp per row) ----------------
__global__ void k_w(const float* __restrict__ He, const float* __restrict__ p) {
    int row  = blockIdx.x * 8 + (threadIdx.x >> 5);
    int lane = threadIdx.x & 31;
    const float* r = He + (size_t)row * D;
    float s = 0.f;
#pragma unroll
    for (int j = 0; j < 4; j++) {
        int k = lane + 32 * j;
        s += r[k] * __ldg(p + k);
    }
#pragma unroll
    for (int o = 16; o > 0; o >>= 1) s += __shfl_xor_sync(0xffffffffu, s, o);
    if (lane == 0) g_w[row] = s;
}

// ---------------- kernel 2: Tw = tf32(T*w), Ttf = tf32(T)  (one read of T) ----------------
__global__ void __launch_bounds__(256)
k_prep(const float* __restrict__ T) {
    const size_t stride = (size_t)gridDim.x * blockDim.x;   // 524288
    size_t c = (size_t)blockIdx.x * blockDim.x + threadIdx.x;
#pragma unroll
    for (int it = 0; it < 8; it++, c += stride) {
        size_t e  = c * 4;
        int col = (int)(e & (size_t)(NE - 1));
        float4 t = *reinterpret_cast<const float4*>(T + e);
        float4 w = *reinterpret_cast<const float4*>(g_w + col);
        float4 o, r;
        o.x = __uint_as_float(f2tf32(t.x * w.x));
        o.y = __uint_as_float(f2tf32(t.y * w.y));
        o.z = __uint_as_float(f2tf32(t.z * w.z));
        o.w = __uint_as_float(f2tf32(t.w * w.w));
        r.x = __uint_as_float(f2tf32(t.x));
        r.y = __uint_as_float(f2tf32(t.y));
        r.z = __uint_as_float(f2tf32(t.z));
        r.w = __uint_as_float(f2tf32(t.w));
        *reinterpret_cast<float4*>(g_Tw + e)  = o;
        *reinterpret_cast<float4*>(g_Ttf + e) = r;
    }
}

// ---------------- kernel 3: HW = H_v @ weight  (8 rows per block) ----------------
__global__ void k_hw(const float* __restrict__ Hv, const float* __restrict__ W) {
    __shared__ float sh[8][D];
    int r0  = blockIdx.x * 8;
    int tid = threadIdx.x;  // 128
#pragma unroll
    for (int r = 0; r < 8; r++) sh[r][tid] = Hv[(size_t)(r0 + r) * D + tid];
    __syncthreads();
    float acc[8] = {};
    for (int k = 0; k < D; k++) {
        float wk = W[k * D + tid];
#pragma unroll
        for (int r = 0; r < 8; r++) acc[r] += sh[r][k] * wk;
    }
#pragma unroll
    for (int r = 0; r < 8; r++) g_HW[(r0 + r) * D + tid] = acc[r];
}

// ---------------- kernel 4: big symmetric GEMM, 512 thr, 4x4 grid, 32x32 tiles ----
// C = Tw @ Ttf^T  (2048x2048, K=8192), upper-tri 128x128 blocks only.
// 16 warps, each owns a 32x32 sub-tile over the FULL K. Small acc (32 regs)
// frees registers for fragment double-buffering -> LDSM(sk+1) overlaps HMMA(sk),
// so the smem crossbar and tensor pipe run concurrently instead of in phases.
#define BM 128
#define BK 32
#define ASTRIDE (BK + 4)                 // 36 floats; LDSM phases conflict-free
#define STAGE_FLOATS (2 * BM * ASTRIDE)  // A + B tile per stage = 9216 floats
#define NSTAGE 3
#define SMEM_BYTES (NSTAGE * STAGE_FLOATS * 4)  // 110592 B

__global__ void __launch_bounds__(512, 1)
k_gemm1(const float* __restrict__ adj_v) {
    // decode upper-triangular block index (16x16 grid of 128-blocks)
    int l = blockIdx.x, bm = 0, rem = 16;
    while (l >= rem) { l -= rem; bm++; rem--; }
    int bn = bm + l;

    extern __shared__ float smem[];
    uint32_t sbase = smem_u32(smem);

    int tid  = threadIdx.x;
    int warp = tid >> 5, lane = tid & 31;
    int wm = warp & 3, wn = warp >> 2;     // 4x4 grid: warp = 32 rows x 32 cols
    int gid = lane >> 2, tig = lane & 3;

    const float* gA = g_Tw  + (size_t)(bm * BM) * NE;
    const float* gB = g_Ttf + (size_t)(bn * BM) * NE;

    float acc[2][4][4];
#pragma unroll
    for (int m = 0; m < 2; m++)
#pragma unroll
        for (int n = 0; n < 4; n++)
#pragma unroll
            for (int q = 0; q < 4; q++) acc[m][n][q] = 0.f;

    const int nkt = NE / BK;  // 256

    // stage loader: 1024 16B-chunks per operand over 512 threads (2 each)
    auto load_stage = [&](int s, int kt) {
        uint32_t sA = sbase + (uint32_t)(s * STAGE_FLOATS) * 4u;
        uint32_t sB = sA + (uint32_t)(BM * ASTRIDE) * 4u;
#pragma unroll
        for (int i = 0; i < 2; i++) {
            int c = i * 512 + tid;
            int row = c >> 3, c16 = c & 7;
            uint32_t soff = (uint32_t)(row * ASTRIDE + c16 * 4) * 4u;
            cp_async16(sA + soff, gA + (size_t)row * NE + kt * BK + c16 * 4);
            cp_async16(sB + soff, gB + (size_t)row * NE + kt * BK + c16 * 4);
        }
        cp_commit();
    };

    load_stage(0, 0);
    load_stage(1, 1);

    // LDSM per-lane address offsets (bytes within a stage); ks adds 32B each
    uint32_t aoff = (uint32_t)((wm * 32 + ((lane >> 3) & 1) * 8 + (lane & 7)) * ASTRIDE
                               + (lane >> 4) * 4) * 4u;
    uint32_t boff = (uint32_t)((wn * 32 + (lane >> 4) * 8 + (lane & 7)) * ASTRIDE
                               + ((lane >> 3) & 1) * 4) * 4u
                  + (uint32_t)(BM * ASTRIDE) * 4u;

    for (int kt = 0; kt < nkt; kt++) {
        if (kt + 1 < nkt) cp_wait1(); else cp_wait0();
        __syncthreads();
        int s = kt % NSTAGE;
        if (kt + 2 < nkt) load_stage((kt + 2) % NSTAGE, kt + 2);

        uint32_t stb = sbase + (uint32_t)(s * STAGE_FLOATS) * 4u;
        uint32_t aBase = stb + aoff;
        uint32_t bBase = stb + boff;

        uint32_t af[2][2][4], bf[2][4][2];

        // fragment loader for one ks into buffer `buf` (3 ldsm4 total)
        auto ldfrag = [&](int buf, int ks) {
            uint32_t ka = aBase + (uint32_t)(ks * 32);
            ldsm4(af[buf][0], ka);
            ldsm4(af[buf][1], ka + 16u * ASTRIDE * 4u);
            uint32_t kb = bBase + (uint32_t)(ks * 32);
#pragma unroll
            for (int j = 0; j < 2; j++) {
                uint32_t r[4];
                ldsm4(r, kb + (uint32_t)j * (16u * ASTRIDE * 4u));
                bf[buf][2 * j][0]     = r[0];
                bf[buf][2 * j][1]     = r[1];
                bf[buf][2 * j + 1][0] = r[2];
                bf[buf][2 * j + 1][1] = r[3];
            }
        };

        ldfrag(0, 0);
#pragma unroll
        for (int ks = 0; ks < 4; ks++) {
            if (ks < 3) ldfrag((ks + 1) & 1, ks + 1);   // overlap with HMMA below
            int b = ks & 1;
#pragma unroll
            for (int m = 0; m < 2; m++)
#pragma unroll
                for (int n = 0; n < 4; n++) mma_tf32(acc[m][n], af[b][m], bf[b][n]);
        }
    }

    // epilogue: mask + adj_v multiply; mirror into (bn,bm) block when off-diagonal
    bool offdiag = (bm != bn);
#pragma unroll
    for (int m = 0; m < 2; m++) {
        int i0 = bm * BM + wm * 32 + m * 16 + gid;
#pragma unroll
        for (int n = 0; n < 4; n++) {
            int j0 = bn * BM + wn * 32 + n * 8 + 2 * tig;
#pragma unroll
            for (int q = 0; q < 4; q++) {
                int i = i0 + (q >> 1) * 8;
                int j = j0 + (q & 1);
                float v = acc[m][n][q];
                float m1 = (i == j) ? 1.0f : v;
                g_adjA[(size_t)i * NV + j] = m1 * adj_v[(size_t)i * NV + j];
                if (offdiag)  // i != j guaranteed
                    g_adjA[(size_t)j * NV + i] = v * adj_v[(size_t)j * NV + i];
            }
        }
    }
}

// ---------------- kernel 5: ret = adjA @ HW + bias (pipelined fp32 SIMT) ----------------
#define BK2 32
#define H_FLOATS (BK2 * D)           // 4096 floats (HW tile)
#define A_STRIDE 36
#define A_FLOATS (16 * A_STRIDE)     // 576 floats
#define STG2_FLOATS (H_FLOATS + A_FLOATS)   // 4672
#define NSTG2 3
#define SMEM2_BYTES (NSTG2 * STG2_FLOATS * 4)  // 56064 B

__global__ void __launch_bounds__(256, 1)
k_gemm2(const float* __restrict__ bias, float* __restrict__ out) {
    extern __shared__ float sm2[];
    uint32_t sb = smem_u32(sm2);

    int tid  = threadIdx.x;
    int warp = tid >> 5, lane = tid & 31;
    int colb = (warp & 3) * 32 + (lane & 7) * 4;
    int rowb = (warp >> 2) * 8 + (lane >> 3) * 2;
    int r0   = blockIdx.x * 16;

    const int nkt = NV / BK2;  // 64

    auto load_stage = [&](int s, int kt) {
        uint32_t base = sb + (uint32_t)(s * STG2_FLOATS) * 4u;
#pragma unroll
        for (int i = 0; i < 4; i++) {
            int c = i * 256 + tid;
            int row = c >> 5, cic = c & 31;
            cp_async16(base + (uint32_t)(row * D + cic * 4) * 4u,
                       g_HW + (size_t)(kt * BK2 + row) * D + cic * 4);
        }
        if (tid < 128) {
            int row = tid >> 3, cic = tid & 7;
            cp_async16(base + (uint32_t)(H_FLOATS + row * A_STRIDE + cic * 4) * 4u,
                       g_adjA + (size_t)(r0 + row) * NV + kt * BK2 + cic * 4);
        }
        cp_commit();
    };

    load_stage(0, 0);
    load_stage(1, 1);

    float4 acc0 = {0.f, 0.f, 0.f, 0.f};
    float4 acc1 = {0.f, 0.f, 0.f, 0.f};

    for (int kt = 0; kt < nkt; kt++) {
        if (kt + 1 < nkt) cp_wait1(); else cp_wait0();
        __syncthreads();
        int s = kt % NSTG2;
        if (kt + 2 < nkt) load_stage((kt + 2) % NSTG2, kt + 2);

        const float* sH = sm2 + s * STG2_FLOATS;
        const float* sA = sH + H_FLOATS;
        const float* a0p = sA + rowb * A_STRIDE;
        const float* a1p = a0p + A_STRIDE;

#pragma unroll
        for (int k4 = 0; k4 < BK2 / 4; k4++) {
            float4 a0 = *reinterpret_cast<const float4*>(a0p + k4 * 4);
            float4 a1 = *reinterpret_cast<const float4*>(a1p + k4 * 4);
#pragma unroll
            for (int kk = 0; kk < 4; kk++) {
                float4 h = *reinterpret_cast<const float4*>(sH + (k4 * 4 + kk) * D + colb);
                float av0 = (kk == 0) ? a0.x : (kk == 1) ? a0.y : (kk == 2) ? a0.z : a0.w;
                float av1 = (kk == 0) ? a1.x : (kk == 1) ? a1.y : (kk == 2) ? a1.z : a1.w;
                acc0.x += av0 * h.x; acc0.y += av0 * h.y;
                acc0.z += av0 * h.z; acc0.w += av0 * h.w;
                acc1.x += av1 * h.x; acc1.y += av1 * h.y;
                acc1.z += av1 * h.z; acc1.w += av1 * h.w;
            }
        }
    }

    float4 b = *reinterpret_cast<const float4*>(bias + colb);
    acc0.x += b.x; acc0.y += b.y; acc0.z += b.z; acc0.w += b.w;
    acc1.x += b.x; acc1.y += b.y; acc1.z += b.z; acc1.w += b.w;
    *reinterpret_cast<float4*>(out + (size_t)(r0 + rowb) * D + colb)     = acc0;
    *reinterpret_cast<float4*>(out + (size_t)(r0 + rowb + 1) * D + colb) = acc1;
}

// ---------------- launch ----------------
extern "C" void kernel_launch(void* const* d_in, const int* in_sizes, int n_in,
                              void* d_out, int out_size) {
    const float* H_v   = (const float*)d_in[0];
    const float* H_e   = (const float*)d_in[1];
    // d_in[2] = adj_e : UNUSED by the reference graph (node_layer branch)
    const float* adj_v = (const float*)d_in[3];
    const float* T     = (const float*)d_in[4];
    const float* W     = (const float*)d_in[5];
    const float* p     = (const float*)d_in[6];
    const float* bias  = (const float*)d_in[7];
    float* out = (float*)d_out;

    k_w<<<NE / 8, 256>>>(H_e, p);
    k_prep<<<2048, 256>>>(T);
    k_hw<<<NV / 8, 128>>>(H_v, W);

    cudaFuncSetAttribute(k_gemm1, cudaFuncAttributeMaxDynamicSharedMemorySize, SMEM_BYTES);
    k_gemm1<<<136, 512, SMEM_BYTES>>>(adj_v);

    cudaFuncSetAttribute(k_gemm2, cudaFuncAttributeMaxDynamicSharedMemorySize, SMEM2_BYTES);
    k_gemm2<<<NV / 16, 256, SMEM2_BYTES>>>(bias, out);

    // second output: H_e passthrough, concatenated after ret
    if (out_size >= NV * D + NE * D) {
        cudaMemcpyAsync(out + NV * D, H_e, (size_t)NE * D * sizeof(float),
                        cudaMemcpyDeviceToDevice, 0);
    }
}

// round 11
// speedup vs baseline: 1.1883x; 1.1883x over previous
#include <cuda_runtime.h>
#include <cstdint>

#define NV 2048
#define NE 8192
#define D  128

// ---------------- device scratch (static: no runtime allocation) ----------------
__device__ __align__(16) float g_w[NE];                    // 32 KB
__device__ __align__(16) float g_Tw[(size_t)NV * NE];      // 64 MB  tf32(T*w)
__device__ __align__(16) float g_Ttf[(size_t)NV * NE];     // 64 MB  tf32(T)
__device__ __align__(16) float g_adjA[(size_t)NV * NV];    // 16 MB
__device__ __align__(16) float g_HW[NV * D];               // 1 MB

// ---------------- helpers ----------------
__device__ __forceinline__ uint32_t f2tf32(float x) {
    uint32_t u;
    asm("cvt.rna.tf32.f32 %0, %1;" : "=r"(u) : "f"(x));
    return u;
}

__device__ __forceinline__ void mma_tf32(float* d, const uint32_t* a, const uint32_t* b) {
    asm volatile(
        "mma.sync.aligned.m16n8k8.row.col.f32.tf32.tf32.f32 "
        "{%0,%1,%2,%3}, {%4,%5,%6,%7}, {%8,%9}, {%0,%1,%2,%3};\n"
        : "+f"(d[0]), "+f"(d[1]), "+f"(d[2]), "+f"(d[3])
        : "r"(a[0]), "r"(a[1]), "r"(a[2]), "r"(a[3]), "r"(b[0]), "r"(b[1]));
}

__device__ __forceinline__ void ldsm4(uint32_t* r, uint32_t saddr) {
    asm volatile("ldmatrix.sync.aligned.m8n8.x4.shared.b16 {%0,%1,%2,%3}, [%4];"
                 : "=r"(r[0]), "=r"(r[1]), "=r"(r[2]), "=r"(r[3]) : "r"(saddr));
}

__device__ __forceinline__ void cp_async16(uint32_t saddr, const void* g) {
    asm volatile("cp.async.cg.shared.global [%0], [%1], 16;\n" :: "r"(saddr), "l"(g));
}
__device__ __forceinline__ void cp_commit() { asm volatile("cp.async.commit_group;\n" ::: "memory"); }
__device__ __forceinline__ void cp_wait1()  { asm volatile("cp.async.wait_group 1;\n" ::: "memory"); }
__device__ __forceinline__ void cp_wait0()  { asm volatile("cp.async.wait_group 0;\n" ::: "memory"); }

__device__ __forceinline__ uint32_t smem_u32(const void* p) {
    uint32_t a;
    asm("{ .reg .u64 t; cvta.to.shared.u64 t, %1; cvt.u32.u64 %0, t; }" : "=r"(a) : "l"(p));
    return a;
}

// group-scoped named barrier: 256 threads of group g rendezvous on barrier g+1
__device__ __forceinline__ void gbar(int id) {
    asm volatile("bar.sync %0, %1;" :: "r"(id), "r"(256) : "memory");
}

// ---------------- kernel 1: w = H_e @ p  (warp per row) ----------------
__global__ void k_w(const float* __restrict__ He, const float* __restrict__ p) {
    int row  = blockIdx.x * 8 + (threadIdx.x >> 5);
    int lane = threadIdx.x & 31;
    const float* r = He + (size_t)row * D;
    float s = 0.f;
#pragma unroll
    for (int j = 0; j < 4; j++) {
        int k = lane + 32 * j;
        s += r[k] * __ldg(p + k);
    }
#pragma unroll
    for (int o = 16; o > 0; o >>= 1) s += __shfl_xor_sync(0xffffffffu, s, o);
    if (lane == 0) g_w[row] = s;
}

// ---------------- kernel 2: Tw = tf32(T*w), Ttf = tf32(T)  (one read of T) ----------------
__global__ void __launch_bounds__(256)
k_prep(const float* __restrict__ T) {
    const size_t stride = (size_t)gridDim.x * blockDim.x;   // 524288
    size_t c = (size_t)blockIdx.x * blockDim.x + threadIdx.x;
#pragma unroll
    for (int it = 0; it < 8; it++, c += stride) {
        size_t e  = c * 4;
        int col = (int)(e & (size_t)(NE - 1));
        float4 t = *reinterpret_cast<const float4*>(T + e);
        float4 w = *reinterpret_cast<const float4*>(g_w + col);
        float4 o, r;
        o.x = __uint_as_float(f2tf32(t.x * w.x));
        o.y = __uint_as_float(f2tf32(t.y * w.y));
        o.z = __uint_as_float(f2tf32(t.z * w.z));
        o.w = __uint_as_float(f2tf32(t.w * w.w));
        r.x = __uint_as_float(f2tf32(t.x));
        r.y = __uint_as_float(f2tf32(t.y));
        r.z = __uint_as_float(f2tf32(t.z));
        r.w = __uint_as_float(f2tf32(t.w));
        *reinterpret_cast<float4*>(g_Tw + e)  = o;
        *reinterpret_cast<float4*>(g_Ttf + e) = r;
    }
}

// ---------------- kernel 3: HW = H_v @ weight  (8 rows per block) ----------------
__global__ void k_hw(const float* __restrict__ Hv, const float* __restrict__ W) {
    __shared__ float sh[8][D];
    int r0  = blockIdx.x * 8;
    int tid = threadIdx.x;  // 128
#pragma unroll
    for (int r = 0; r < 8; r++) sh[r][tid] = Hv[(size_t)(r0 + r) * D + tid];
    __syncthreads();
    float acc[8] = {};
    for (int k = 0; k < D; k++) {
        float wk = W[k * D + tid];
#pragma unroll
        for (int r = 0; r < 8; r++) acc[r] += sh[r][k] * wk;
    }
#pragma unroll
    for (int r = 0; r < 8; r++) g_HW[(r0 + r) * D + tid] = acc[r];
}

// ---------------- kernel 4: symmetric GEMM, two autonomous 8-warp pipelines ----
// C = Tw @ Ttf^T  (2048x2048, K=8192), upper-tri 128x128 blocks only.
// Group g (8 warps, 4x2 grid of 32x64 tiles) computes K-half [g*4096,(g+1)*4096)
// with its OWN 3-stage cp.async ring and group-scoped named barriers, so the
// two pipelines phase-shift and fill each other's stall tails on the SM.
#define BM 128
#define BK 32
#define ASTRIDE (BK + 4)                 // 36 floats; LDSM phases conflict-free
#define STAGE_FLOATS (2 * BM * ASTRIDE)  // A + B tile per stage = 9216 floats
#define NSTAGE 3
#define GROUP_FLOATS (NSTAGE * STAGE_FLOATS)     // 27648
#define SMEM_BYTES (2 * GROUP_FLOATS * 4)        // 221184 B
#define CSTRIDE 132                      // epilogue reduce buffer row stride

__global__ void __launch_bounds__(512, 1)
k_gemm1(const float* __restrict__ adj_v) {
    // decode upper-triangular block index (16x16 grid of 128-blocks)
    int l = blockIdx.x, bm = 0, rem = 16;
    while (l >= rem) { l -= rem; bm++; rem--; }
    int bn = bm + l;

    extern __shared__ float smem[];
    uint32_t sbase = smem_u32(smem);

    int tid  = threadIdx.x;
    int warp = tid >> 5, lane = tid & 31;
    int grp  = warp >> 3;                  // 0/1: K-half + pipeline id
    int gtid = tid & 255;                  // thread id within group
    int w8   = warp & 7;
    int wm = w8 & 3, wn = w8 >> 2;         // 4x2 grid: warp = 32 rows x 64 cols
    int gid = lane >> 2, tig = lane & 3;

    const float* gA = g_Tw  + (size_t)(bm * BM) * NE + grp * (NE / 2);
    const float* gB = g_Ttf + (size_t)(bn * BM) * NE + grp * (NE / 2);
    uint32_t gbase = sbase + (uint32_t)(grp * GROUP_FLOATS) * 4u;
    int bar = grp + 1;

    float acc[2][8][4];
#pragma unroll
    for (int m = 0; m < 2; m++)
#pragma unroll
        for (int n = 0; n < 8; n++)
#pragma unroll
            for (int q = 0; q < 4; q++) acc[m][n][q] = 0.f;

    const int nkt = (NE / 2) / BK;  // 128 iterations per group

    // group stage loader: 1024 16B-chunks per operand over 256 threads (4 each)
    auto load_stage = [&](int s, int kt) {
        uint32_t sA = gbase + (uint32_t)(s * STAGE_FLOATS) * 4u;
        uint32_t sB = sA + (uint32_t)(BM * ASTRIDE) * 4u;
#pragma unroll
        for (int i = 0; i < 4; i++) {
            int c = i * 256 + gtid;
            int row = c >> 3, c16 = c & 7;
            uint32_t soff = (uint32_t)(row * ASTRIDE + c16 * 4) * 4u;
            cp_async16(sA + soff, gA + (size_t)row * NE + kt * BK + c16 * 4);
            cp_async16(sB + soff, gB + (size_t)row * NE + kt * BK + c16 * 4);
        }
        cp_commit();
    };

    load_stage(0, 0);
    load_stage(1, 1);

    // LDSM per-lane address offsets (bytes within a stage); ks adds 32B each
    uint32_t aoff = (uint32_t)((wm * 32 + ((lane >> 3) & 1) * 8 + (lane & 7)) * ASTRIDE
                               + (lane >> 4) * 4) * 4u;
    uint32_t boff = (uint32_t)((wn * 64 + (lane >> 4) * 8 + (lane & 7)) * ASTRIDE
                               + ((lane >> 3) & 1) * 4) * 4u
                  + (uint32_t)(BM * ASTRIDE) * 4u;

    for (int kt = 0; kt < nkt; kt++) {
        if (kt + 1 < nkt) cp_wait1(); else cp_wait0();
        gbar(bar);
        int s = kt % NSTAGE;
        if (kt + 2 < nkt) load_stage((kt + 2) % NSTAGE, kt + 2);

        uint32_t stb = gbase + (uint32_t)(s * STAGE_FLOATS) * 4u;
        uint32_t aBase = stb + aoff;
        uint32_t bBase = stb + boff;

#pragma unroll
        for (int ks = 0; ks < 4; ks++) {
            uint32_t af[2][4], bf[8][2];
            uint32_t ka = aBase + (uint32_t)(ks * 32);
            ldsm4(af[0], ka);
            ldsm4(af[1], ka + 16u * ASTRIDE * 4u);
            uint32_t kb = bBase + (uint32_t)(ks * 32);
#pragma unroll
            for (int j = 0; j < 4; j++) {
                uint32_t r[4];
                ldsm4(r, kb + (uint32_t)j * (16u * ASTRIDE * 4u));
                bf[2 * j][0]     = r[0];
                bf[2 * j][1]     = r[1];
                bf[2 * j + 1][0] = r[2];
                bf[2 * j + 1][1] = r[3];
            }
#pragma unroll
            for (int m = 0; m < 2; m++)
#pragma unroll
                for (int n = 0; n < 8; n++) mma_tf32(acc[m][n], af[m], bf[n]);
        }
        gbar(bar);   // protect stage s from being overwritten before all warps consumed it
    }

    // ---- combine group partials through smem (group 1's stage area), then epilogue ----
    __syncthreads();
    float* cbuf = smem + GROUP_FLOATS;   // 128 x CSTRIDE floats = 67.6 KB, fits
    if (grp == 1) {
#pragma unroll
        for (int m = 0; m < 2; m++) {
            int il = wm * 32 + m * 16 + gid;
#pragma unroll
            for (int n = 0; n < 8; n++) {
                int jl = wn * 64 + n * 8 + 2 * tig;
#pragma unroll
                for (int q = 0; q < 4; q++)
                    cbuf[(il + (q >> 1) * 8) * CSTRIDE + jl + (q & 1)] = acc[m][n][q];
            }
        }
    }
    __syncthreads();

    if (grp == 0) {
        bool offdiag = (bm != bn);
#pragma unroll
        for (int m = 0; m < 2; m++) {
            int il0 = wm * 32 + m * 16 + gid;
#pragma unroll
            for (int n = 0; n < 8; n++) {
                int jl0 = wn * 64 + n * 8 + 2 * tig;
#pragma unroll
                for (int q = 0; q < 4; q++) {
                    int il = il0 + (q >> 1) * 8;
                    int jl = jl0 + (q & 1);
                    int i = bm * BM + il;
                    int j = bn * BM + jl;
                    float v = acc[m][n][q] + cbuf[il * CSTRIDE + jl];
                    float m1 = (i == j) ? 1.0f : v;
                    g_adjA[(size_t)i * NV + j] = m1 * adj_v[(size_t)i * NV + j];
                    if (offdiag)  // i != j guaranteed
                        g_adjA[(size_t)j * NV + i] = v * adj_v[(size_t)j * NV + i];
                }
            }
        }
    }
}

// ---------------- kernel 5: ret = adjA @ HW + bias (pipelined fp32 SIMT) ----------------
#define BK2 32
#define H_FLOATS (BK2 * D)           // 4096 floats (HW tile)
#define A_STRIDE 36
#define A_FLOATS (16 * A_STRIDE)     // 576 floats
#define STG2_FLOATS (H_FLOATS + A_FLOATS)   // 4672
#define NSTG2 3
#define SMEM2_BYTES (NSTG2 * STG2_FLOATS * 4)  // 56064 B

__global__ void __launch_bounds__(256, 1)
k_gemm2(const float* __restrict__ bias, float* __restrict__ out) {
    extern __shared__ float sm2[];
    uint32_t sb = smem_u32(sm2);

    int tid  = threadIdx.x;
    int warp = tid >> 5, lane = tid & 31;
    int colb = (warp & 3) * 32 + (lane & 7) * 4;
    int rowb = (warp >> 2) * 8 + (lane >> 3) * 2;
    int r0   = blockIdx.x * 16;

    const int nkt = NV / BK2;  // 64

    auto load_stage = [&](int s, int kt) {
        uint32_t base = sb + (uint32_t)(s * STG2_FLOATS) * 4u;
#pragma unroll
        for (int i = 0; i < 4; i++) {
            int c = i * 256 + tid;
            int row = c >> 5, cic = c & 31;
            cp_async16(base + (uint32_t)(row * D + cic * 4) * 4u,
                       g_HW + (size_t)(kt * BK2 + row) * D + cic * 4);
        }
        if (tid < 128) {
            int row = tid >> 3, cic = tid & 7;
            cp_async16(base + (uint32_t)(H_FLOATS + row * A_STRIDE + cic * 4) * 4u,
                       g_adjA + (size_t)(r0 + row) * NV + kt * BK2 + cic * 4);
        }
        cp_commit();
    };

    load_stage(0, 0);
    load_stage(1, 1);

    float4 acc0 = {0.f, 0.f, 0.f, 0.f};
    float4 acc1 = {0.f, 0.f, 0.f, 0.f};

    for (int kt = 0; kt < nkt; kt++) {
        if (kt + 1 < nkt) cp_wait1(); else cp_wait0();
        __syncthreads();
        int s = kt % NSTG2;
        if (kt + 2 < nkt) load_stage((kt + 2) % NSTG2, kt + 2);

        const float* sH = sm2 + s * STG2_FLOATS;
        const float* sA = sH + H_FLOATS;
        const float* a0p = sA + rowb * A_STRIDE;
        const float* a1p = a0p + A_STRIDE;

#pragma unroll
        for (int k4 = 0; k4 < BK2 / 4; k4++) {
            float4 a0 = *reinterpret_cast<const float4*>(a0p + k4 * 4);
            float4 a1 = *reinterpret_cast<const float4*>(a1p + k4 * 4);
#pragma unroll
            for (int kk = 0; kk < 4; kk++) {
                float4 h = *reinterpret_cast<const float4*>(sH + (k4 * 4 + kk) * D + colb);
                float av0 = (kk == 0) ? a0.x : (kk == 1) ? a0.y : (kk == 2) ? a0.z : a0.w;
                float av1 = (kk == 0) ? a1.x : (kk == 1) ? a1.y : (kk == 2) ? a1.z : a1.w;
                acc0.x += av0 * h.x; acc0.y += av0 * h.y;
                acc0.z += av0 * h.z; acc0.w += av0 * h.w;
                acc1.x += av1 * h.x; acc1.y += av1 * h.y;
                acc1.z += av1 * h.z; acc1.w += av1 * h.w;
            }
        }
    }

    float4 b = *reinterpret_cast<const float4*>(bias + colb);
    acc0.x += b.x; acc0.y += b.y; acc0.z += b.z; acc0.w += b.w;
    acc1.x += b.x; acc1.y += b.y; acc1.z += b.z; acc1.w += b.w;
    *reinterpret_cast<float4*>(out + (size_t)(r0 + rowb) * D + colb)     = acc0;
    *reinterpret_cast<float4*>(out + (size_t)(r0 + rowb + 1) * D + colb) = acc1;
}

// ---------------- launch ----------------
extern "C" void kernel_launch(void* const* d_in, const int* in_sizes, int n_in,
                              void* d_out, int out_size) {
    const float* H_v   = (const float*)d_in[0];
    const float* H_e   = (const float*)d_in[1];
    // d_in[2] = adj_e : UNUSED by the reference graph (node_layer branch)
    const float* adj_v = (const float*)d_in[3];
    const float* T     = (const float*)d_in[4];
    const float* W     = (const float*)d_in[5];
    const float* p     = (const float*)d_in[6];
    const float* bias  = (const float*)d_in[7];
    float* out = (float*)d_out;

    k_w<<<NE / 8, 256>>>(H_e, p);
    k_prep<<<2048, 256>>>(T);
    k_hw<<<NV / 8, 128>>>(H_v, W);

    cudaFuncSetAttribute(k_gemm1, cudaFuncAttributeMaxDynamicSharedMemorySize, SMEM_BYTES);
    k_gemm1<<<136, 512, SMEM_BYTES>>>(adj_v);

    cudaFuncSetAttribute(k_gemm2, cudaFuncAttributeMaxDynamicSharedMemorySize, SMEM2_BYTES);
    k_gemm2<<<NV / 16, 256, SMEM2_BYTES>>>(bias, out);

    // second output: H_e passthrough, concatenated after ret
    if (out_size >= NV * D + NE * D) {
        cudaMemcpyAsync(out + NV * D, H_e, (size_t)NE * D * sizeof(float),
                        cudaMemcpyDeviceToDevice, 0);
    }
}